// round 14
// baseline (speedup 1.0000x reference)
#include <cuda_runtime.h>
#include <cuda_fp16.h>
#include <math.h>
#include <stdint.h>

#define BB 2048
#define LL 96
#define DD 256
#define EE 131072
#define GG 768    /* 3*DD */
#define PITW 264  /* halves per 256-half row (conflict-free ldmatrix) */
#define PITA 72   /* halves per 64-half A-chunk row */

#define WS_HALVES (9 * 32 * PITW)              /* 76032 halves = 152064 B */
#define AT_HALVES (2 * 2 * 128 * PITA)         /* 36864 halves = 73728 B  */
#define BIAS_OFF  (WS_HALVES + AT_HALVES)      /* half offset of bias region */
#define SMEM_PERSIST (BIAS_OFF * 2 + 160 * 4)  /* 226432 bytes */
#define SMEM_INGEMM (256 * PITW * 2)           /* 135168 bytes: A 128 + B 2x64 rows */

// ---------------- static scratch ---------------------------------------------
__device__ __align__(128) __half g_seq16[(size_t)BB * LL * DD]; // padding rows stay 0
__device__ __align__(128) __half g_xph[(size_t)LL * BB * GG];   // fp16 xp, bias-folded
__device__ __align__(128) __half g_h1h[2][BB * DD];
__device__ __align__(128) __half g_h2h[2][BB * DD];
__device__ __align__(128) __half g_w16[4][GG * DD];  // wih0, whh0, wih1, whh1
__device__ __align__(128) float  g_bias0[GG];        // bih0 (+bhh0 for r,z gates)
__device__ int g_counts[BB];     // zeroed at end of k_persist (and by module load)
__device__ __align__(256) unsigned g_tbar[16 * 64];  // per-m-tile arrivals, 256B stride
__device__ unsigned g_gbar;                          // global leader arrivals

// ---------------- helpers ----------------------------------------------------
__device__ __forceinline__ uint32_t sptr(const void* p) {
    return (uint32_t)__cvta_generic_to_shared(p);
}
__device__ __forceinline__ void ldsm4(uint32_t r[4], uint32_t addr) {
    asm volatile("ldmatrix.sync.aligned.m8n8.x4.shared.b16 {%0,%1,%2,%3}, [%4];"
                 : "=r"(r[0]), "=r"(r[1]), "=r"(r[2]), "=r"(r[3]) : "r"(addr));
}
__device__ __forceinline__ void mma16816(float c[4], const uint32_t a[4],
                                         uint32_t b0, uint32_t b1) {
    asm volatile(
        "mma.sync.aligned.m16n8k16.row.col.f32.f16.f16.f32 "
        "{%0,%1,%2,%3}, {%4,%5,%6,%7}, {%8,%9}, {%0,%1,%2,%3};"
        : "+f"(c[0]), "+f"(c[1]), "+f"(c[2]), "+f"(c[3])
        : "r"(a[0]), "r"(a[1]), "r"(a[2]), "r"(a[3]), "r"(b0), "r"(b1));
}
__device__ __forceinline__ void cpa16(void* dst, const void* src) {
    asm volatile("cp.async.cg.shared.global [%0], [%1], 16;\n"
                 :: "r"(sptr(dst)), "l"(src));
}
__device__ __forceinline__ void cpcommit() { asm volatile("cp.async.commit_group;\n"); }
template <int N> __device__ __forceinline__ void cpwait() {
    asm volatile("cp.async.wait_group %0;\n" :: "n"(N));
}
__device__ __forceinline__ void redrel(unsigned* p) {
    asm volatile("red.release.gpu.global.add.u32 [%0], %1;" :: "l"(p), "r"(1u) : "memory");
}
__device__ __forceinline__ unsigned ldacq(unsigned* p) {
    unsigned v;
    asm volatile("ld.acquire.gpu.global.u32 %0, [%1];" : "=r"(v) : "l"(p) : "memory");
    return v;
}
__device__ __forceinline__ float tanhx(float x) {
    float y;
    asm("tanh.approx.f32 %0, %1;" : "=f"(y) : "f"(x));
    return y;
}
__device__ __forceinline__ float sigm(float x) { return 0.5f * tanhx(0.5f * x) + 0.5f; }

// ---------------- launch 0: init + weight convert + histogram ----------------
__global__ void k_init(const float* __restrict__ a, const float* __restrict__ b,
                       const float* __restrict__ c, const float* __restrict__ d,
                       const float* __restrict__ bih0, const float* __restrict__ bhh0,
                       const int* __restrict__ idx) {
    int i = blockIdx.x * blockDim.x + threadIdx.x;   // grid covers BB*DD = 524288
    if (i < BB * DD) {
        g_h1h[0][i] = __float2half(0.f);
        g_h2h[0][i] = __float2half(0.f);
    }
    if (i < 16 * 64) g_tbar[i] = 0u;
    if (i == 0) g_gbar = 0u;
    if (i < GG) g_bias0[i] = bih0[i] + (i < 2 * DD ? bhh0[i] : 0.f);
    if (i < GG * DD) {
        g_w16[0][i] = __float2half_rn(a[i]);
        g_w16[1][i] = __float2half_rn(b[i]);
        g_w16[2][i] = __float2half_rn(c[i]);
        g_w16[3][i] = __float2half_rn(d[i]);
    }
    if (i < EE) atomicAdd(&g_counts[idx[i]], 1);
}

// ---------------- launch 1: per-group stable sort + scatter -------------------
__global__ void k_sortscatter(const float* __restrict__ ts, const float* __restrict__ x) {
    int b = blockIdx.x;
    __shared__ float st[LL];
    __shared__ int smap[LL];
    __shared__ int red[128];
    int t = threadIdx.x;
    int partial = 0;
    for (int j = t; j < b; j += 128) partial += g_counts[j];
    red[t] = partial;
    for (int l = t; l < LL; l += 128) smap[l] = -1;
    __syncthreads();
    for (int s = 64; s > 0; s >>= 1) {
        if (t < s) red[t] += red[t + s];
        __syncthreads();
    }
    int off = red[0];
    int cnt = g_counts[b];
    if (t < cnt) st[t] = ts[off + t];
    __syncthreads();
    if (t < cnt) {
        float ti = st[t];
        int rank = 0;
        for (int j = 0; j < cnt; j++) {
            float tj = st[j];
            rank += (tj < ti) || (tj == ti && j < t);
        }
        int slot = rank + (ti > 0.f ? (LL - cnt) : 0);
        smap[slot] = off + t;
    }
    __syncthreads();
    for (int it = t; it < LL * 64; it += 128) {
        int l = it >> 6, c = it & 63;
        int src = smap[l];
        if (src < 0) continue;
        float4 v = reinterpret_cast<const float4*>(x + (size_t)src * DD)[c];
        __half2* dst = reinterpret_cast<__half2*>(g_seq16 + ((size_t)b * LL + l) * DD);
        dst[c * 2]     = __floats2half2_rn(v.x, v.y);
        dst[c * 2 + 1] = __floats2half2_rn(v.z, v.w);
    }
}

// ---------------- launch 2: A-stationary input GEMM ---------------------------
__global__ void __launch_bounds__(256) k_ingemm16() {
    extern __shared__ __align__(16) __half gsm[];
    __half* As  = gsm;                   // 128 x PITW
    __half* Bs0 = gsm + 128 * PITW;      // 64 x PITW
    __half* Bs1 = Bs0 + 64 * PITW;
    const __half* __restrict__ wb = g_w16[0];
    int m0 = blockIdx.x * 128;
    int tid = threadIdx.x, warp = tid >> 5, lane = tid & 31;
    int rowq = lane >> 2, colp = (lane & 3) * 2;

#pragma unroll
    for (int j = 0; j < 16; j++) {
        int p = tid + j * 256;
        int row = p >> 5, seg = (p & 31) * 8;
        cpa16(&As[row * PITW + seg], &g_seq16[(size_t)(m0 + row) * DD + seg]);
    }
    cpcommit();
#pragma unroll
    for (int j = 0; j < 8; j++) {
        int p = tid + j * 256;
        int row = p >> 5, seg = (p & 31) * 8;
        cpa16(&Bs0[row * PITW + seg], &wb[(size_t)row * DD + seg]);
    }
    cpcommit();

    for (int nc = 0; nc < 12; nc++) {
        __half* Bcur = (nc & 1) ? Bs1 : Bs0;
        if (nc < 11) {
            __half* Bnxt = (nc & 1) ? Bs0 : Bs1;
#pragma unroll
            for (int j = 0; j < 8; j++) {
                int p = tid + j * 256;
                int row = p >> 5, seg = (p & 31) * 8;
                cpa16(&Bnxt[row * PITW + seg],
                      &wb[(size_t)((nc + 1) * 64 + row) * DD + seg]);
            }
            cpcommit();
            cpwait<1>();
        } else cpwait<0>();
        __syncthreads();
        float acc[4][2][4] = {};
#pragma unroll
        for (int ks = 0; ks < 16; ks++) {
            int kq = ks * 16 + ((lane >> 4) << 3);
            uint32_t a[4];
            ldsm4(a, sptr(&As[(warp * 16 + (lane & 15)) * PITW + kq]));
#pragma unroll
            for (int j = 0; j < 4; j++) {
                uint32_t b[4];
                ldsm4(b, sptr(&Bcur[(j * 16 + (lane & 15)) * PITW + kq]));
                mma16816(acc[j][0], a, b[0], b[2]);
                mma16816(acc[j][1], a, b[1], b[3]);
            }
        }
        __syncthreads();
#pragma unroll
        for (int ci = 0; ci < 2; ci++) {
            int m = m0 + warp * 16 + rowq + ci * 8;
            int b_ = m / LL, l = m % LL;
            __half* dst = &g_xph[((size_t)l * BB + b_) * GG];
#pragma unroll
            for (int j = 0; j < 4; j++) {
#pragma unroll
                for (int jj = 0; jj < 2; jj++) {
                    int n = nc * 64 + j * 16 + jj * 8 + colp;
                    *(__half2*)&dst[n] = __floats2half2_rn(
                        acc[j][jj][ci * 2 + 0] + __ldg(&g_bias0[n]),
                        acc[j][jj][ci * 2 + 1] + __ldg(&g_bias0[n + 1]));
                }
            }
        }
    }
}

// ---------------- launch 3: persistent fused recurrence -----------------------
// Tree barrier: 16 per-tile counters (8 arrivals) + 1 global (16 leader
// arrivals). Exact lockstep semantics; parallelized arrival reduction.
__device__ __forceinline__ void gridbar(int mt, bool leader, unsigned k1) {
    __syncthreads();
    if (threadIdx.x == 0) {
        unsigned* tp = &g_tbar[mt * 64];
        redrel(tp);
        if (leader) {
            while (ldacq(tp) < 8u * k1) {}
            redrel(&g_gbar);
        }
        while (ldacq(&g_gbar) < 16u * k1) {}
    }
    __syncthreads();
}

__global__ void __launch_bounds__(512, 1) k_persist(
    const float* __restrict__ bhh0, const float* __restrict__ bih1,
    const float* __restrict__ bhh1, float* __restrict__ out) {
    extern __shared__ __align__(16) __half sm[];
#define WSM(i) (sm + (i) * 32 * PITW)
#define ATM(stg, t) (sm + WS_HALVES + ((stg) * 2 + (t)) * 128 * PITA)
    float* bsm = (float*)(sm + BIAS_OFF);
    int cid = blockIdx.x;
    int mt = cid >> 3;
    int m0 = mt * 128, d0 = (cid & 7) * 32;
    bool leader = (cid & 7) == 0;
    int tid = threadIdx.x, warp = tid >> 5, lane = tid & 31;
    int wm = warp & 7, wn = warp >> 3;          // m-slice, d-half
    int rowq = lane >> 2, colp = (lane & 3) * 2;

    // resident weights: [0..2]=whh0, [3..5]=wih1, [6..8]=whh1
    for (int idx = tid; idx < 9 * 32 * 32; idx += 512) {
        int mat = idx >> 10, rem = idx & 1023;
        int r = rem >> 5, c16 = rem & 31;
        const __half* src;
        if (mat < 3)      src = &g_w16[1][(size_t)(mat * DD + d0 + r) * DD + c16 * 8];
        else if (mat < 6) src = &g_w16[2][(size_t)((mat - 3) * DD + d0 + r) * DD + c16 * 8];
        else              src = &g_w16[3][(size_t)((mat - 6) * DD + d0 + r) * DD + c16 * 8];
        cpa16(&WSM(mat)[r * PITW + c16 * 8], src);
    }
    cpcommit();
    // biases -> smem: [0]=bhh0_n, [32]=b1r, [64]=b1z, [96]=bih1_n, [128]=bhh1_n
    if (tid < 32) {
        int dd = d0 + tid;
        bsm[tid]       = bhh0[2 * DD + dd];
        bsm[32 + tid]  = bih1[dd] + bhh1[dd];
        bsm[64 + tid]  = bih1[DD + dd] + bhh1[DD + dd];
        bsm[96 + tid]  = bih1[2 * DD + dd];
        bsm[128 + tid] = bhh1[2 * DD + dd];
    }
    cpwait<0>();
    __syncthreads();

    float h1s[8] = {}, h2s[8] = {}, asum[8] = {};

    for (int k = 0; k <= 96; k++) {
        const bool do1 = (k < 96), do2 = (k >= 1);
        const __half* __restrict__ hA1 = g_h1h[k & 1];
        const __half* __restrict__ hA2 = g_h2h[(k + 1) & 1];

        auto loadchunk = [&](int c, int stg) {
            int kk = c * 64;
            __half* A1 = ATM(stg, 0);
            __half* A2 = ATM(stg, 1);
#pragma unroll
            for (int j = 0; j < 2; j++) {
                int p = tid + j * 512;             // 0..1023
                int row = p >> 3, seg = (p & 7) * 8;
                cpa16(&A1[row * PITA + seg], &hA1[(size_t)(m0 + row) * DD + kk + seg]);
                cpa16(&A2[row * PITA + seg], &hA2[(size_t)(m0 + row) * DD + kk + seg]);
            }
            cpcommit();
        };

        loadchunk(0, 0);

        // prefetch xp tile into registers (latency hides under GEMM)
        uint32_t xpr[2][2][3];
        if (do1) {
            const __half* xph = g_xph + (size_t)k * BB * GG;
#pragma unroll
            for (int ci = 0; ci < 2; ci++)
#pragma unroll
                for (int ni = 0; ni < 2; ni++) {
                    int m = m0 + wm * 16 + rowq + ci * 8;
                    const __half* base = xph + (size_t)m * GG + d0 + wn * 16 + ni * 8 + colp;
#pragma unroll
                    for (int g = 0; g < 3; g++)
                        xpr[ci][ni][g] = __ldg((const uint32_t*)(base + g * DD));
                }
        }

        float j1a[3][2][4] = {};     // r,z,n  (h1 @ whh0)
        float j2r[2][4] = {}, j2z[2][4] = {}, j2xn[2][4] = {}, j2hn[2][4] = {};

        for (int c = 0; c < 4; c++) {
            cpwait<0>();
            __syncthreads();
            // issue next chunk AFTER the sync: all warps have finished reading
            // the stage about to be overwritten -> trailing sync eliminated.
            if (c < 3) loadchunk(c + 1, (c + 1) & 1);
            const __half* A1 = ATM(c & 1, 0);
            const __half* A2 = ATM(c & 1, 1);
#pragma unroll
            for (int ks = 0; ks < 4; ks++) {
                int kq = ks * 16 + ((lane >> 4) << 3);
                uint32_t a1[4], a2[4];
                ldsm4(a1, sptr(&A1[(wm * 16 + (lane & 15)) * PITA + kq]));
                if (do2) ldsm4(a2, sptr(&A2[(wm * 16 + (lane & 15)) * PITA + kq]));
                uint32_t brow = (wn * 16 + (lane & 15)) * PITW + c * 64 + kq;
                if (do1) {
#pragma unroll
                    for (int g = 0; g < 3; g++) {
                        uint32_t b[4];
                        ldsm4(b, sptr(&WSM(g)[brow]));
                        mma16816(j1a[g][0], a1, b[0], b[2]);
                        mma16816(j1a[g][1], a1, b[1], b[3]);
                    }
                }
                if (do2) {
                    uint32_t b[4];
                    ldsm4(b, sptr(&WSM(3)[brow]));
                    mma16816(j2r[0], a1, b[0], b[2]);
                    mma16816(j2r[1], a1, b[1], b[3]);
                    ldsm4(b, sptr(&WSM(4)[brow]));
                    mma16816(j2z[0], a1, b[0], b[2]);
                    mma16816(j2z[1], a1, b[1], b[3]);
                    ldsm4(b, sptr(&WSM(5)[brow]));
                    mma16816(j2xn[0], a1, b[0], b[2]);
                    mma16816(j2xn[1], a1, b[1], b[3]);
                    ldsm4(b, sptr(&WSM(6)[brow]));
                    mma16816(j2r[0], a2, b[0], b[2]);
                    mma16816(j2r[1], a2, b[1], b[3]);
                    ldsm4(b, sptr(&WSM(7)[brow]));
                    mma16816(j2z[0], a2, b[0], b[2]);
                    mma16816(j2z[1], a2, b[1], b[3]);
                    ldsm4(b, sptr(&WSM(8)[brow]));
                    mma16816(j2hn[0], a2, b[0], b[2]);
                    mma16816(j2hn[1], a2, b[1], b[3]);
                }
            }
        }

        // epilogue layer 1 -> h1(k+1)
        if (do1) {
            __half* __restrict__ hh = g_h1h[(k + 1) & 1];
            int id = 0;
#pragma unroll
            for (int ci = 0; ci < 2; ci++)
#pragma unroll
                for (int ni = 0; ni < 2; ni++) {
                    int m = m0 + wm * 16 + rowq + ci * 8;
                    int d = d0 + wn * 16 + ni * 8 + colp;
                    int jb = wn * 16 + ni * 8 + colp;
                    float2 fr = __half22float2(*(__half2*)&xpr[ci][ni][0]);
                    float2 fz = __half22float2(*(__half2*)&xpr[ci][ni][1]);
                    float2 fn = __half22float2(*(__half2*)&xpr[ci][ni][2]);
                    float2 bn = *(float2*)&bsm[jb];
                    float hv[2];
#pragma unroll
                    for (int q = 0; q < 2; q++) {
                        float xr = q ? fr.y : fr.x, xz = q ? fz.y : fz.x, xn = q ? fn.y : fn.x;
                        float bnn = q ? bn.y : bn.x;
                        float r = sigm(xr + j1a[0][ni][ci * 2 + q]);
                        float z = sigm(xz + j1a[1][ni][ci * 2 + q]);
                        float nn = tanhx(xn + r * (j1a[2][ni][ci * 2 + q] + bnn));
                        hv[q] = (1.f - z) * nn + z * h1s[id];
                        h1s[id] = hv[q];
                        id++;
                    }
                    *(__half2*)&hh[(size_t)m * DD + d] = __floats2half2_rn(hv[0], hv[1]);
                }
        }

        // epilogue layer 2 -> h2, running sum
        if (do2) {
            __half* __restrict__ hh = g_h2h[k & 1];
            int id = 0;
#pragma unroll
            for (int ci = 0; ci < 2; ci++)
#pragma unroll
                for (int ni = 0; ni < 2; ni++) {
                    int m = m0 + wm * 16 + rowq + ci * 8;
                    int d = d0 + wn * 16 + ni * 8 + colp;
                    int jb = wn * 16 + ni * 8 + colp;
                    float2 br = *(float2*)&bsm[32 + jb];
                    float2 bz = *(float2*)&bsm[64 + jb];
                    float2 bni = *(float2*)&bsm[96 + jb];
                    float2 bnh = *(float2*)&bsm[128 + jb];
                    float hv[2];
#pragma unroll
                    for (int q = 0; q < 2; q++) {
                        float r = sigm(j2r[ni][ci * 2 + q] + (q ? br.y : br.x));
                        float z = sigm(j2z[ni][ci * 2 + q] + (q ? bz.y : bz.x));
                        float nn = tanhx(j2xn[ni][ci * 2 + q] + (q ? bni.y : bni.x) +
                                         r * (j2hn[ni][ci * 2 + q] + (q ? bnh.y : bnh.x)));
                        hv[q] = (1.f - z) * nn + z * h2s[id];
                        h2s[id] = hv[q];
                        asum[id] += hv[q];
                        id++;
                    }
                    *(__half2*)&hh[(size_t)m * DD + d] = __floats2half2_rn(hv[0], hv[1]);
                }
        }

        if (k < 96) gridbar(mt, leader, (unsigned)(k + 1));
    }

    // write mean
    int id = 0;
#pragma unroll
    for (int ci = 0; ci < 2; ci++)
#pragma unroll
        for (int ni = 0; ni < 2; ni++) {
            int m = m0 + wm * 16 + rowq + ci * 8;
            int d = d0 + wn * 16 + ni * 8 + colp;
            float2 v;
            v.x = asum[id] * (1.f / (float)LL);
            v.y = asum[id + 1] * (1.f / (float)LL);
            id += 2;
            *(float2*)&out[(size_t)m * DD + d] = v;
        }

    // reset counts for the next graph replay (safe: counts unused in this kernel)
    if (cid < 4) g_counts[cid * 512 + tid] = 0;
}

// ---------------- launch ------------------------------------------------------
extern "C" void kernel_launch(void* const* d_in, const int* in_sizes, int n_in,
                              void* d_out, int out_size) {
    const float* x    = (const float*)d_in[0];
    const float* ts   = (const float*)d_in[1];
    const float* wih0 = (const float*)d_in[2];
    const float* whh0 = (const float*)d_in[3];
    const float* bih0 = (const float*)d_in[4];
    const float* bhh0 = (const float*)d_in[5];
    const float* wih1 = (const float*)d_in[6];
    const float* whh1 = (const float*)d_in[7];
    const float* bih1 = (const float*)d_in[8];
    const float* bhh1 = (const float*)d_in[9];
    const int*   idx  = (const int*)d_in[10];

    static int smem_set = 0;
    if (!smem_set) {
        cudaFuncSetAttribute(k_persist, cudaFuncAttributeMaxDynamicSharedMemorySize,
                             SMEM_PERSIST);
        cudaFuncSetAttribute(k_ingemm16, cudaFuncAttributeMaxDynamicSharedMemorySize,
                             SMEM_INGEMM);
        smem_set = 1;
    }

    k_init<<<(BB * DD + 255) / 256, 256>>>(wih0, whh0, wih1, whh1, bih0, bhh0, idx);
    k_sortscatter<<<BB, 128>>>(ts, x);
    k_ingemm16<<<BB * LL / 128, 256, SMEM_INGEMM>>>();
    k_persist<<<128, 512, SMEM_PERSIST>>>(bhh0, bih1, bhh1, (float*)d_out);
}

// round 15
// speedup vs baseline: 1.0651x; 1.0651x over previous
#include <cuda_runtime.h>
#include <cuda_fp16.h>
#include <math.h>
#include <stdint.h>

#define BB 2048
#define LL 96
#define DD 256
#define EE 131072
#define GG 768    /* 3*DD */
#define PITW 264  /* halves per 256-half row (conflict-free ldmatrix) */
#define PITA 72   /* halves per 64-half A-chunk row */

#define WS_HALVES (9 * 32 * PITW)              /* 76032 halves = 152064 B */
#define AT_HALVES (2 * 2 * 128 * PITA)         /* 36864 halves = 73728 B  */
#define BIAS_OFF  (WS_HALVES + AT_HALVES)      /* half offset of bias region */
#define SMEM_PERSIST (BIAS_OFF * 2 + 160 * 4)  /* 226432 bytes */
#define SMEM_INGEMM (256 * PITW * 2)           /* 135168 bytes: A 128 + B 2x64 rows */

// ---------------- static scratch ---------------------------------------------
__device__ __align__(128) __half g_seq16[(size_t)BB * LL * DD]; // padding rows stay 0
__device__ __align__(128) __half g_xph[(size_t)LL * BB * GG];   // fp16 xp, bias-folded
__device__ __align__(128) __half g_h1h[2][BB * DD];
__device__ __align__(128) __half g_h2h[2][BB * DD];
__device__ __align__(128) __half g_w16[4][GG * DD];  // wih0, whh0, wih1, whh1
__device__ __align__(128) float  g_bias0[GG];        // bih0 (+bhh0 for r,z gates)
__device__ int g_counts[BB];     // zeroed at end of k_persist (and by module load)
__device__ __align__(256) unsigned g_tbar[16 * 64];  // per-m-tile barrier, 256B stride

// ---------------- helpers ----------------------------------------------------
__device__ __forceinline__ uint32_t sptr(const void* p) {
    return (uint32_t)__cvta_generic_to_shared(p);
}
__device__ __forceinline__ void ldsm4(uint32_t r[4], uint32_t addr) {
    asm volatile("ldmatrix.sync.aligned.m8n8.x4.shared.b16 {%0,%1,%2,%3}, [%4];"
                 : "=r"(r[0]), "=r"(r[1]), "=r"(r[2]), "=r"(r[3]) : "r"(addr));
}
__device__ __forceinline__ void mma16816(float c[4], const uint32_t a[4],
                                         uint32_t b0, uint32_t b1) {
    asm volatile(
        "mma.sync.aligned.m16n8k16.row.col.f32.f16.f16.f32 "
        "{%0,%1,%2,%3}, {%4,%5,%6,%7}, {%8,%9}, {%0,%1,%2,%3};"
        : "+f"(c[0]), "+f"(c[1]), "+f"(c[2]), "+f"(c[3])
        : "r"(a[0]), "r"(a[1]), "r"(a[2]), "r"(a[3]), "r"(b0), "r"(b1));
}
__device__ __forceinline__ void cpa16(void* dst, const void* src) {
    asm volatile("cp.async.cg.shared.global [%0], [%1], 16;\n"
                 :: "r"(sptr(dst)), "l"(src));
}
__device__ __forceinline__ void cpcommit() { asm volatile("cp.async.commit_group;\n"); }
template <int N> __device__ __forceinline__ void cpwait() {
    asm volatile("cp.async.wait_group %0;\n" :: "n"(N));
}
__device__ __forceinline__ void redrel(unsigned* p) {
    asm volatile("red.release.gpu.global.add.u32 [%0], %1;" :: "l"(p), "r"(1u) : "memory");
}
__device__ __forceinline__ unsigned ldacq(unsigned* p) {
    unsigned v;
    asm volatile("ld.acquire.gpu.global.u32 %0, [%1];" : "=r"(v) : "l"(p) : "memory");
    return v;
}
__device__ __forceinline__ float tanhx(float x) {
    float y;
    asm("tanh.approx.f32 %0, %1;" : "=f"(y) : "f"(x));
    return y;
}
__device__ __forceinline__ float sigm(float x) { return 0.5f * tanhx(0.5f * x) + 0.5f; }

// ---------------- launch 0: init + weight convert + histogram ----------------
__global__ void k_init(const float* __restrict__ a, const float* __restrict__ b,
                       const float* __restrict__ c, const float* __restrict__ d,
                       const float* __restrict__ bih0, const float* __restrict__ bhh0,
                       const int* __restrict__ idx) {
    int i = blockIdx.x * blockDim.x + threadIdx.x;   // grid covers BB*DD = 524288
    if (i < BB * DD) {
        g_h1h[0][i] = __float2half(0.f);
        g_h2h[0][i] = __float2half(0.f);
    }
    if (i < 16 * 64) g_tbar[i] = 0u;
    if (i < GG) g_bias0[i] = bih0[i] + (i < 2 * DD ? bhh0[i] : 0.f);
    if (i < GG * DD) {
        g_w16[0][i] = __float2half_rn(a[i]);
        g_w16[1][i] = __float2half_rn(b[i]);
        g_w16[2][i] = __float2half_rn(c[i]);
        g_w16[3][i] = __float2half_rn(d[i]);
    }
    if (i < EE) atomicAdd(&g_counts[idx[i]], 1);
}

// ---------------- launch 1: per-group stable sort + scatter -------------------
__global__ void k_sortscatter(const float* __restrict__ ts, const float* __restrict__ x) {
    int b = blockIdx.x;
    __shared__ float st[LL];
    __shared__ int smap[LL];
    __shared__ int red[128];
    int t = threadIdx.x;
    int partial = 0;
    for (int j = t; j < b; j += 128) partial += g_counts[j];
    red[t] = partial;
    for (int l = t; l < LL; l += 128) smap[l] = -1;
    __syncthreads();
    for (int s = 64; s > 0; s >>= 1) {
        if (t < s) red[t] += red[t + s];
        __syncthreads();
    }
    int off = red[0];
    int cnt = g_counts[b];
    if (t < cnt) st[t] = ts[off + t];
    __syncthreads();
    if (t < cnt) {
        float ti = st[t];
        int rank = 0;
        for (int j = 0; j < cnt; j++) {
            float tj = st[j];
            rank += (tj < ti) || (tj == ti && j < t);
        }
        int slot = rank + (ti > 0.f ? (LL - cnt) : 0);
        smap[slot] = off + t;
    }
    __syncthreads();
    for (int it = t; it < LL * 64; it += 128) {
        int l = it >> 6, c = it & 63;
        int src = smap[l];
        if (src < 0) continue;
        float4 v = reinterpret_cast<const float4*>(x + (size_t)src * DD)[c];
        __half2* dst = reinterpret_cast<__half2*>(g_seq16 + ((size_t)b * LL + l) * DD);
        dst[c * 2]     = __floats2half2_rn(v.x, v.y);
        dst[c * 2 + 1] = __floats2half2_rn(v.z, v.w);
    }
}

// ---------------- launch 2: A-stationary input GEMM ---------------------------
__global__ void __launch_bounds__(256) k_ingemm16() {
    extern __shared__ __align__(16) __half gsm[];
    __half* As  = gsm;                   // 128 x PITW
    __half* Bs0 = gsm + 128 * PITW;      // 64 x PITW
    __half* Bs1 = Bs0 + 64 * PITW;
    const __half* __restrict__ wb = g_w16[0];
    int m0 = blockIdx.x * 128;
    int tid = threadIdx.x, warp = tid >> 5, lane = tid & 31;
    int rowq = lane >> 2, colp = (lane & 3) * 2;

#pragma unroll
    for (int j = 0; j < 16; j++) {
        int p = tid + j * 256;
        int row = p >> 5, seg = (p & 31) * 8;
        cpa16(&As[row * PITW + seg], &g_seq16[(size_t)(m0 + row) * DD + seg]);
    }
    cpcommit();
#pragma unroll
    for (int j = 0; j < 8; j++) {
        int p = tid + j * 256;
        int row = p >> 5, seg = (p & 31) * 8;
        cpa16(&Bs0[row * PITW + seg], &wb[(size_t)row * DD + seg]);
    }
    cpcommit();

    for (int nc = 0; nc < 12; nc++) {
        __half* Bcur = (nc & 1) ? Bs1 : Bs0;
        if (nc < 11) {
            __half* Bnxt = (nc & 1) ? Bs0 : Bs1;
#pragma unroll
            for (int j = 0; j < 8; j++) {
                int p = tid + j * 256;
                int row = p >> 5, seg = (p & 31) * 8;
                cpa16(&Bnxt[row * PITW + seg],
                      &wb[(size_t)((nc + 1) * 64 + row) * DD + seg]);
            }
            cpcommit();
            cpwait<1>();
        } else cpwait<0>();
        __syncthreads();
        float acc[4][2][4] = {};
#pragma unroll
        for (int ks = 0; ks < 16; ks++) {
            int kq = ks * 16 + ((lane >> 4) << 3);
            uint32_t a[4];
            ldsm4(a, sptr(&As[(warp * 16 + (lane & 15)) * PITW + kq]));
#pragma unroll
            for (int j = 0; j < 4; j++) {
                uint32_t b[4];
                ldsm4(b, sptr(&Bcur[(j * 16 + (lane & 15)) * PITW + kq]));
                mma16816(acc[j][0], a, b[0], b[2]);
                mma16816(acc[j][1], a, b[1], b[3]);
            }
        }
        __syncthreads();
#pragma unroll
        for (int ci = 0; ci < 2; ci++) {
            int m = m0 + warp * 16 + rowq + ci * 8;
            int b_ = m / LL, l = m % LL;
            __half* dst = &g_xph[((size_t)l * BB + b_) * GG];
#pragma unroll
            for (int j = 0; j < 4; j++) {
#pragma unroll
                for (int jj = 0; jj < 2; jj++) {
                    int n = nc * 64 + j * 16 + jj * 8 + colp;
                    *(__half2*)&dst[n] = __floats2half2_rn(
                        acc[j][jj][ci * 2 + 0] + __ldg(&g_bias0[n]),
                        acc[j][jj][ci * 2 + 1] + __ldg(&g_bias0[n + 1]));
                }
            }
        }
    }
}

// ---------------- launch 3: persistent fused recurrence -----------------------
// R13 structure byte-for-byte, except the barrier: 16 INDEPENDENT per-m-tile
// 8-CTA barriers (the only cross-CTA dependencies are intra-m-tile).
__device__ __forceinline__ void tilebar(unsigned* tp, unsigned want) {
    __syncthreads();
    if (threadIdx.x == 0) {
        redrel(tp);
        while (ldacq(tp) < want) {}
    }
    __syncthreads();
}

__global__ void __launch_bounds__(512, 1) k_persist(
    const float* __restrict__ bhh0, const float* __restrict__ bih1,
    const float* __restrict__ bhh1, float* __restrict__ out) {
    extern __shared__ __align__(16) __half sm[];
#define WSM(i) (sm + (i) * 32 * PITW)
#define ATM(stg, t) (sm + WS_HALVES + ((stg) * 2 + (t)) * 128 * PITA)
    float* bsm = (float*)(sm + BIAS_OFF);
    int cid = blockIdx.x;
    int mt = cid >> 3;
    int m0 = mt * 128, d0 = (cid & 7) * 32;
    unsigned* tbp = &g_tbar[mt * 64];
    int tid = threadIdx.x, warp = tid >> 5, lane = tid & 31;
    int wm = warp & 7, wn = warp >> 3;          // m-slice, d-half
    int rowq = lane >> 2, colp = (lane & 3) * 2;

    // resident weights: [0..2]=whh0, [3..5]=wih1, [6..8]=whh1
    for (int idx = tid; idx < 9 * 32 * 32; idx += 512) {
        int mat = idx >> 10, rem = idx & 1023;
        int r = rem >> 5, c16 = rem & 31;
        const __half* src;
        if (mat < 3)      src = &g_w16[1][(size_t)(mat * DD + d0 + r) * DD + c16 * 8];
        else if (mat < 6) src = &g_w16[2][(size_t)((mat - 3) * DD + d0 + r) * DD + c16 * 8];
        else              src = &g_w16[3][(size_t)((mat - 6) * DD + d0 + r) * DD + c16 * 8];
        cpa16(&WSM(mat)[r * PITW + c16 * 8], src);
    }
    cpcommit();
    // biases -> smem: [0]=bhh0_n, [32]=b1r, [64]=b1z, [96]=bih1_n, [128]=bhh1_n
    if (tid < 32) {
        int dd = d0 + tid;
        bsm[tid]       = bhh0[2 * DD + dd];
        bsm[32 + tid]  = bih1[dd] + bhh1[dd];
        bsm[64 + tid]  = bih1[DD + dd] + bhh1[DD + dd];
        bsm[96 + tid]  = bih1[2 * DD + dd];
        bsm[128 + tid] = bhh1[2 * DD + dd];
    }
    cpwait<0>();
    __syncthreads();

    float h1s[8] = {}, h2s[8] = {}, asum[8] = {};

    for (int k = 0; k <= 96; k++) {
        const bool do1 = (k < 96), do2 = (k >= 1);
        const __half* __restrict__ hA1 = g_h1h[k & 1];
        const __half* __restrict__ hA2 = g_h2h[(k + 1) & 1];

        auto loadchunk = [&](int c, int stg) {
            int kk = c * 64;
            __half* A1 = ATM(stg, 0);
            __half* A2 = ATM(stg, 1);
#pragma unroll
            for (int j = 0; j < 2; j++) {
                int p = tid + j * 512;             // 0..1023
                int row = p >> 3, seg = (p & 7) * 8;
                cpa16(&A1[row * PITA + seg], &hA1[(size_t)(m0 + row) * DD + kk + seg]);
                cpa16(&A2[row * PITA + seg], &hA2[(size_t)(m0 + row) * DD + kk + seg]);
            }
            cpcommit();
        };

        loadchunk(0, 0);

        // prefetch xp tile into registers (latency hides under GEMM)
        uint32_t xpr[2][2][3];
        if (do1) {
            const __half* xph = g_xph + (size_t)k * BB * GG;
#pragma unroll
            for (int ci = 0; ci < 2; ci++)
#pragma unroll
                for (int ni = 0; ni < 2; ni++) {
                    int m = m0 + wm * 16 + rowq + ci * 8;
                    const __half* base = xph + (size_t)m * GG + d0 + wn * 16 + ni * 8 + colp;
#pragma unroll
                    for (int g = 0; g < 3; g++)
                        xpr[ci][ni][g] = __ldg((const uint32_t*)(base + g * DD));
                }
        }

        float j1a[3][2][4] = {};     // r,z,n  (h1 @ whh0)
        float j2r[2][4] = {}, j2z[2][4] = {}, j2xn[2][4] = {}, j2hn[2][4] = {};

        for (int c = 0; c < 4; c++) {
            if (c < 3) { loadchunk(c + 1, (c + 1) & 1); cpwait<1>(); }
            else cpwait<0>();
            __syncthreads();
            const __half* A1 = ATM(c & 1, 0);
            const __half* A2 = ATM(c & 1, 1);
#pragma unroll
            for (int ks = 0; ks < 4; ks++) {
                int kq = ks * 16 + ((lane >> 4) << 3);
                uint32_t a1[4], a2[4];
                ldsm4(a1, sptr(&A1[(wm * 16 + (lane & 15)) * PITA + kq]));
                if (do2) ldsm4(a2, sptr(&A2[(wm * 16 + (lane & 15)) * PITA + kq]));
                uint32_t brow = (wn * 16 + (lane & 15)) * PITW + c * 64 + kq;
                if (do1) {
#pragma unroll
                    for (int g = 0; g < 3; g++) {
                        uint32_t b[4];
                        ldsm4(b, sptr(&WSM(g)[brow]));
                        mma16816(j1a[g][0], a1, b[0], b[2]);
                        mma16816(j1a[g][1], a1, b[1], b[3]);
                    }
                }
                if (do2) {
                    uint32_t b[4];
                    ldsm4(b, sptr(&WSM(3)[brow]));
                    mma16816(j2r[0], a1, b[0], b[2]);
                    mma16816(j2r[1], a1, b[1], b[3]);
                    ldsm4(b, sptr(&WSM(4)[brow]));
                    mma16816(j2z[0], a1, b[0], b[2]);
                    mma16816(j2z[1], a1, b[1], b[3]);
                    ldsm4(b, sptr(&WSM(5)[brow]));
                    mma16816(j2xn[0], a1, b[0], b[2]);
                    mma16816(j2xn[1], a1, b[1], b[3]);
                    ldsm4(b, sptr(&WSM(6)[brow]));
                    mma16816(j2r[0], a2, b[0], b[2]);
                    mma16816(j2r[1], a2, b[1], b[3]);
                    ldsm4(b, sptr(&WSM(7)[brow]));
                    mma16816(j2z[0], a2, b[0], b[2]);
                    mma16816(j2z[1], a2, b[1], b[3]);
                    ldsm4(b, sptr(&WSM(8)[brow]));
                    mma16816(j2hn[0], a2, b[0], b[2]);
                    mma16816(j2hn[1], a2, b[1], b[3]);
                }
            }
            __syncthreads();
        }

        // epilogue layer 1 -> h1(k+1)
        if (do1) {
            __half* __restrict__ hh = g_h1h[(k + 1) & 1];
            int id = 0;
#pragma unroll
            for (int ci = 0; ci < 2; ci++)
#pragma unroll
                for (int ni = 0; ni < 2; ni++) {
                    int m = m0 + wm * 16 + rowq + ci * 8;
                    int d = d0 + wn * 16 + ni * 8 + colp;
                    int jb = wn * 16 + ni * 8 + colp;
                    float2 fr = __half22float2(*(__half2*)&xpr[ci][ni][0]);
                    float2 fz = __half22float2(*(__half2*)&xpr[ci][ni][1]);
                    float2 fn = __half22float2(*(__half2*)&xpr[ci][ni][2]);
                    float2 bn = *(float2*)&bsm[jb];
                    float hv[2];
#pragma unroll
                    for (int q = 0; q < 2; q++) {
                        float xr = q ? fr.y : fr.x, xz = q ? fz.y : fz.x, xn = q ? fn.y : fn.x;
                        float bnn = q ? bn.y : bn.x;
                        float r = sigm(xr + j1a[0][ni][ci * 2 + q]);
                        float z = sigm(xz + j1a[1][ni][ci * 2 + q]);
                        float nn = tanhx(xn + r * (j1a[2][ni][ci * 2 + q] + bnn));
                        hv[q] = (1.f - z) * nn + z * h1s[id];
                        h1s[id] = hv[q];
                        id++;
                    }
                    *(__half2*)&hh[(size_t)m * DD + d] = __floats2half2_rn(hv[0], hv[1]);
                }
        }

        // epilogue layer 2 -> h2, running sum
        if (do2) {
            __half* __restrict__ hh = g_h2h[k & 1];
            int id = 0;
#pragma unroll
            for (int ci = 0; ci < 2; ci++)
#pragma unroll
                for (int ni = 0; ni < 2; ni++) {
                    int m = m0 + wm * 16 + rowq + ci * 8;
                    int d = d0 + wn * 16 + ni * 8 + colp;
                    int jb = wn * 16 + ni * 8 + colp;
                    float2 br = *(float2*)&bsm[32 + jb];
                    float2 bz = *(float2*)&bsm[64 + jb];
                    float2 bni = *(float2*)&bsm[96 + jb];
                    float2 bnh = *(float2*)&bsm[128 + jb];
                    float hv[2];
#pragma unroll
                    for (int q = 0; q < 2; q++) {
                        float r = sigm(j2r[ni][ci * 2 + q] + (q ? br.y : br.x));
                        float z = sigm(j2z[ni][ci * 2 + q] + (q ? bz.y : bz.x));
                        float nn = tanhx(j2xn[ni][ci * 2 + q] + (q ? bni.y : bni.x) +
                                         r * (j2hn[ni][ci * 2 + q] + (q ? bnh.y : bnh.x)));
                        hv[q] = (1.f - z) * nn + z * h2s[id];
                        h2s[id] = hv[q];
                        asum[id] += hv[q];
                        id++;
                    }
                    *(__half2*)&hh[(size_t)m * DD + d] = __floats2half2_rn(hv[0], hv[1]);
                }
        }

        if (k < 96) tilebar(tbp, 8u * (unsigned)(k + 1));
    }

    // write mean
    int id = 0;
#pragma unroll
    for (int ci = 0; ci < 2; ci++)
#pragma unroll
        for (int ni = 0; ni < 2; ni++) {
            int m = m0 + wm * 16 + rowq + ci * 8;
            int d = d0 + wn * 16 + ni * 8 + colp;
            float2 v;
            v.x = asum[id] * (1.f / (float)LL);
            v.y = asum[id + 1] * (1.f / (float)LL);
            id += 2;
            *(float2*)&out[(size_t)m * DD + d] = v;
        }

    // reset counts for the next graph replay (safe: counts unused in this kernel)
    if (cid < 4) g_counts[cid * 512 + tid] = 0;
}

// ---------------- launch ------------------------------------------------------
extern "C" void kernel_launch(void* const* d_in, const int* in_sizes, int n_in,
                              void* d_out, int out_size) {
    const float* x    = (const float*)d_in[0];
    const float* ts   = (const float*)d_in[1];
    const float* wih0 = (const float*)d_in[2];
    const float* whh0 = (const float*)d_in[3];
    const float* bih0 = (const float*)d_in[4];
    const float* bhh0 = (const float*)d_in[5];
    const float* wih1 = (const float*)d_in[6];
    const float* whh1 = (const float*)d_in[7];
    const float* bih1 = (const float*)d_in[8];
    const float* bhh1 = (const float*)d_in[9];
    const int*   idx  = (const int*)d_in[10];

    static int smem_set = 0;
    if (!smem_set) {
        cudaFuncSetAttribute(k_persist, cudaFuncAttributeMaxDynamicSharedMemorySize,
                             SMEM_PERSIST);
        cudaFuncSetAttribute(k_ingemm16, cudaFuncAttributeMaxDynamicSharedMemorySize,
                             SMEM_INGEMM);
        smem_set = 1;
    }

    k_init<<<(BB * DD + 255) / 256, 256>>>(wih0, whh0, wih1, whh1, bih0, bhh0, idx);
    k_sortscatter<<<BB, 128>>>(ts, x);
    k_ingemm16<<<BB * LL / 128, 256, SMEM_INGEMM>>>();
    k_persist<<<128, 512, SMEM_PERSIST>>>(bhh0, bih1, bhh1, (float*)d_out);
}